// round 8
// baseline (speedup 1.0000x reference)
#include <cuda_runtime.h>
#include <cuda_bf16.h>
#include <math.h>
#include <stdint.h>

#define NN 100000
#define EE 1600000
#define DH 128
#define DOUT 40
#define SCAN_CHUNK 1024
#define SCAN_BLOCKS ((NN + SCAN_CHUNK - 1) / SCAN_CHUNK)   // 98 <= 128

// -------- scratch (static device globals; no dynamic allocation) --------
__device__ float g_ns[NN];
__device__ float g_nd[NN];
__device__ int   g_cnt_src[NN];
__device__ int   g_cnt_dst[NN];
__device__ int   g_roff[NN];
__device__ int   g_cursor[NN];
__device__ int   g_part[128];
__device__ int   g_csr[EE];
__device__ float g_h [(size_t)NN * DH];
__device__ float g_x [(size_t)NN * DH];
__device__ float g_stats[2 * DH];    // sums / sumsq
__device__ float g_coef[2 * DH];     // a / b
__device__ float g_Whi[DH * DH];
__device__ float g_Wlo[DH * DH];

// ---------------------------------------------------------------- util --
__device__ __forceinline__ uint32_t f2tf32(float v) {
    uint32_t r;
    asm("cvt.rna.tf32.f32 %0, %1;" : "=r"(r) : "f"(v));
    return r;
}

__global__ void zeroi(int* __restrict__ p, int n) {
    int i = blockIdx.x * blockDim.x + threadIdx.x;
    if (i < n) p[i] = 0;
}
__global__ void zerof(float* __restrict__ p, int n) {
    int i = blockIdx.x * blockDim.x + threadIdx.x;
    if (i < n) p[i] = 0.0f;
}

// split W into tf32 hi + tf32(lo) parts
__global__ void split_tf32(const float* __restrict__ W, float* __restrict__ hi,
                           float* __restrict__ lo, int n) {
    int i = blockIdx.x * blockDim.x + threadIdx.x;
    if (i < n) {
        float v = W[i];
        uint32_t h = f2tf32(v);
        float hf = __uint_as_float(h);
        hi[i] = hf;
        lo[i] = __uint_as_float(f2tf32(v - hf));
    }
}

// ------------------------------------------------------------ CSR build --
__global__ void count_kernel(const int* __restrict__ src, const int* __restrict__ dst,
                             int* __restrict__ cs, int* __restrict__ cd, int nE) {
    int i = blockIdx.x * blockDim.x + threadIdx.x;
    if (i < nE) {
        atomicAdd(&cs[src[i]], 1);
        atomicAdd(&cd[dst[i]], 1);
    }
}

__global__ void norms_kernel(const int* __restrict__ cs, const int* __restrict__ cd,
                             float* __restrict__ ns, float* __restrict__ nd, int n) {
    int i = blockIdx.x * blockDim.x + threadIdx.x;
    if (i < n) {
        ns[i] = rsqrtf(fmaxf((float)cs[i], 1.0f));
        nd[i] = rsqrtf(fmaxf((float)cd[i], 1.0f));
    }
}

__global__ void scan_partial(const int* __restrict__ cnt, int* __restrict__ part, int n) {
    __shared__ int sm[256];
    int base = blockIdx.x * SCAN_CHUNK;
    int t = threadIdx.x;
    int s = 0;
    for (int i = t; i < SCAN_CHUNK; i += 256) {
        int idx = base + i;
        if (idx < n) s += cnt[idx];
    }
    sm[t] = s; __syncthreads();
    for (int off = 128; off > 0; off >>= 1) {
        if (t < off) sm[t] += sm[t + off];
        __syncthreads();
    }
    if (t == 0) part[blockIdx.x] = sm[0];
}

__global__ void scan_part_ex(int* __restrict__ part, int nb) {
    __shared__ int sm[128];
    int t = threadIdx.x;
    int orig = (t < nb) ? part[t] : 0;
    sm[t] = orig; __syncthreads();
    for (int off = 1; off < 128; off <<= 1) {
        int v = (t >= off) ? sm[t - off] : 0;
        __syncthreads();
        sm[t] += v;
        __syncthreads();
    }
    if (t < nb) part[t] = sm[t] - orig;
}

__global__ void scan_final(const int* __restrict__ cnt, const int* __restrict__ part,
                           int* __restrict__ roff, int* __restrict__ cursor, int n) {
    __shared__ int sm[256];
    int base = blockIdx.x * SCAN_CHUNK;
    int t = threadIdx.x;
    int v[4]; int s = 0;
#pragma unroll
    for (int i = 0; i < 4; i++) {
        int idx = base + t * 4 + i;
        v[i] = (idx < n) ? cnt[idx] : 0;
        s += v[i];
    }
    int orig = s;
    sm[t] = s; __syncthreads();
    for (int off = 1; off < 256; off <<= 1) {
        int x = (t >= off) ? sm[t - off] : 0;
        __syncthreads();
        sm[t] += x;
        __syncthreads();
    }
    int o = part[blockIdx.x] + sm[t] - orig;
#pragma unroll
    for (int i = 0; i < 4; i++) {
        int idx = base + t * 4 + i;
        if (idx < n) { roff[idx] = o; cursor[idx] = o; o += v[i]; }
    }
}

__global__ void scatter_kernel(const int* __restrict__ src, const int* __restrict__ dst,
                               int* __restrict__ cursor, int* __restrict__ csr, int nE) {
    int i = blockIdx.x * blockDim.x + threadIdx.x;
    if (i < nE) {
        int pos = atomicAdd(&cursor[dst[i]], 1);
        csr[pos] = src[i];
    }
}

// ---------------------------------------------- Tensor-core GEMM (3xTF32) --
// C[N,128] = f(A)[N,128] @ W[128,128]
// MODE 0: f(A) = A * ns[:,None]
// MODE 1: f(A) = relu(A*cA + cB) * ns[:,None]
// Block: 256 threads, tile 128 rows x 128 cols, K in 4 chunks of 32.
// SMEM strides: A stride 36 (== 4 mod 32), W stride 136 (== 8 mod 32) give
// conflict-free fragment LDS for the m16n8k8 lane pattern.
#define A_STR 36
#define W_STR 136
#define SM_AHI 0
#define SM_ALO (128 * A_STR)
#define SM_WHI (2 * 128 * A_STR)
#define SM_WLO (2 * 128 * A_STR + 32 * W_STR)
#define GEMM_SMEM ((2 * 128 * A_STR + 2 * 32 * W_STR) * 4)

__device__ __forceinline__ void mma_tf32(float* d, const uint32_t* a, uint32_t b0, uint32_t b1) {
    asm volatile(
        "mma.sync.aligned.m16n8k8.row.col.f32.tf32.tf32.f32 "
        "{%0,%1,%2,%3},{%4,%5,%6,%7},{%8,%9},{%0,%1,%2,%3};"
        : "+f"(d[0]), "+f"(d[1]), "+f"(d[2]), "+f"(d[3])
        : "r"(a[0]), "r"(a[1]), "r"(a[2]), "r"(a[3]), "r"(b0), "r"(b1));
}

template <int MODE>
__global__ void __launch_bounds__(256, 2)
gemm128_tc(const float* __restrict__ A, const float* __restrict__ ns,
           const float* __restrict__ cA, const float* __restrict__ cB,
           const float* __restrict__ Whi, const float* __restrict__ Wlo,
           float* __restrict__ C, int n) {
    extern __shared__ float sm[];
    const int tid = threadIdx.x;
    const int w = tid >> 5;
    const int lane = tid & 31;
    const int g = lane >> 2;       // group id (0..7)
    const int cq = lane & 3;       // thread-in-group (0..3)
    const int wm = w & 3;          // warp row-block (0..3) -> 32 rows
    const int wn = w >> 2;         // warp col-block (0..1) -> 64 cols
    const int r0 = blockIdx.x * 128;

    float acc[2][8][4];
#pragma unroll
    for (int mt = 0; mt < 2; mt++)
#pragma unroll
        for (int nt = 0; nt < 8; nt++)
#pragma unroll
            for (int i = 0; i < 4; i++) acc[mt][nt][i] = 0.0f;

    for (int chunk = 0; chunk < 4; chunk++) {
        const int kbase = chunk * 32;
        __syncthreads();
        // ---- stage A chunk: 128 rows x 32 k, split hi/lo, fused prologue ----
#pragma unroll
        for (int i = 0; i < 4; i++) {
            int idx = tid + i * 256;          // 0..1023
            int row = idx >> 3;               // 0..127
            int kq = idx & 7;                 // float4 index within 32 k
            int grow = r0 + row;
            float4 v;
            float nsr = 0.0f;
            if (grow < n) {
                v = __ldg((const float4*)A + (size_t)grow * 32 + (kbase >> 2) + kq);
                nsr = __ldg(&ns[grow]);
            } else {
                v = make_float4(0.f, 0.f, 0.f, 0.f);
            }
            if (MODE == 1) {
                float4 a4 = __ldg((const float4*)cA + (kbase >> 2) + kq);
                float4 b4 = __ldg((const float4*)cB + (kbase >> 2) + kq);
                v.x = fmaf(v.x, a4.x, b4.x); v.x = v.x > 0.f ? v.x : 0.f;
                v.y = fmaf(v.y, a4.y, b4.y); v.y = v.y > 0.f ? v.y : 0.f;
                v.z = fmaf(v.z, a4.z, b4.z); v.z = v.z > 0.f ? v.z : 0.f;
                v.w = fmaf(v.w, a4.w, b4.w); v.w = v.w > 0.f ? v.w : 0.f;
            }
            v.x *= nsr; v.y *= nsr; v.z *= nsr; v.w *= nsr;
            float hx = __uint_as_float(f2tf32(v.x));
            float hy = __uint_as_float(f2tf32(v.y));
            float hz = __uint_as_float(f2tf32(v.z));
            float hw = __uint_as_float(f2tf32(v.w));
            float4 hi4 = make_float4(hx, hy, hz, hw);
            float4 lo4 = make_float4(__uint_as_float(f2tf32(v.x - hx)),
                                     __uint_as_float(f2tf32(v.y - hy)),
                                     __uint_as_float(f2tf32(v.z - hz)),
                                     __uint_as_float(f2tf32(v.w - hw)));
            *(float4*)&sm[SM_AHI + row * A_STR + kq * 4] = hi4;
            *(float4*)&sm[SM_ALO + row * A_STR + kq * 4] = lo4;
        }
        // ---- stage W chunk: 32 k x 128 cols (hi and lo, precomputed) ----
#pragma unroll
        for (int i = 0; i < 4; i++) {
            int idx = tid + i * 256;          // 0..1023
            int krow = idx >> 5;              // 0..31
            int cq4 = idx & 31;               // float4 col
            float4 vh = __ldg((const float4*)Whi + (size_t)(kbase + krow) * 32 + cq4);
            float4 vl = __ldg((const float4*)Wlo + (size_t)(kbase + krow) * 32 + cq4);
            *(float4*)&sm[SM_WHI + krow * W_STR + cq4 * 4] = vh;
            *(float4*)&sm[SM_WLO + krow * W_STR + cq4 * 4] = vl;
        }
        __syncthreads();

        // ---- compute: 4 k8-steps ----
#pragma unroll
        for (int k8 = 0; k8 < 4; k8++) {
            const int kc = k8 * 8;
            uint32_t ahi[2][4], alo[2][4];
#pragma unroll
            for (int mt = 0; mt < 2; mt++) {
                int rowb = wm * 32 + mt * 16;
                ahi[mt][0] = __float_as_uint(sm[SM_AHI + (rowb + g) * A_STR + kc + cq]);
                ahi[mt][1] = __float_as_uint(sm[SM_AHI + (rowb + g + 8) * A_STR + kc + cq]);
                ahi[mt][2] = __float_as_uint(sm[SM_AHI + (rowb + g) * A_STR + kc + cq + 4]);
                ahi[mt][3] = __float_as_uint(sm[SM_AHI + (rowb + g + 8) * A_STR + kc + cq + 4]);
                alo[mt][0] = __float_as_uint(sm[SM_ALO + (rowb + g) * A_STR + kc + cq]);
                alo[mt][1] = __float_as_uint(sm[SM_ALO + (rowb + g + 8) * A_STR + kc + cq]);
                alo[mt][2] = __float_as_uint(sm[SM_ALO + (rowb + g) * A_STR + kc + cq + 4]);
                alo[mt][3] = __float_as_uint(sm[SM_ALO + (rowb + g + 8) * A_STR + kc + cq + 4]);
            }
#pragma unroll
            for (int nt = 0; nt < 8; nt++) {
                int colb = wn * 64 + nt * 8;
                uint32_t bhi0 = __float_as_uint(sm[SM_WHI + (kc + cq) * W_STR + colb + g]);
                uint32_t bhi1 = __float_as_uint(sm[SM_WHI + (kc + cq + 4) * W_STR + colb + g]);
                uint32_t blo0 = __float_as_uint(sm[SM_WLO + (kc + cq) * W_STR + colb + g]);
                uint32_t blo1 = __float_as_uint(sm[SM_WLO + (kc + cq + 4) * W_STR + colb + g]);
#pragma unroll
                for (int mt = 0; mt < 2; mt++) {
                    mma_tf32(acc[mt][nt], ahi[mt], bhi0, bhi1);
                    mma_tf32(acc[mt][nt], ahi[mt], blo0, blo1);
                    mma_tf32(acc[mt][nt], alo[mt], bhi0, bhi1);
                }
            }
        }
    }

    // ---- epilogue: write C ----
#pragma unroll
    for (int mt = 0; mt < 2; mt++) {
        int row0 = r0 + wm * 32 + mt * 16 + g;
        int row1 = row0 + 8;
#pragma unroll
        for (int nt = 0; nt < 8; nt++) {
            int col = wn * 64 + nt * 8 + cq * 2;
            if (row0 < n)
                *(float2*)&C[(size_t)row0 * 128 + col] = make_float2(acc[mt][nt][0], acc[mt][nt][1]);
            if (row1 < n)
                *(float2*)&C[(size_t)row1 * 128 + col] = make_float2(acc[mt][nt][2], acc[mt][nt][3]);
        }
    }
}

// ------------------------------------------------- GEMM 40 (FFMA) -------
__global__ void gemm40(const float* __restrict__ A, const float* __restrict__ ns,
                       const float* __restrict__ cA, const float* __restrict__ cB,
                       const float* __restrict__ W, float* __restrict__ C, int n) {
    __shared__ __align__(16) float sA[32 * 128];
    const int t = threadIdx.x;
    int r0 = blockIdx.x * 32;
    if (r0 >= n) return;
    int rows = min(32, n - r0);
    for (int i = t; i < rows * 128; i += 320) {
        int r = i >> 7, k = i & 127;
        float v = A[(size_t)(r0 + r) * 128 + k];
        v = fmaf(v, __ldg(&cA[k]), __ldg(&cB[k]));
        v = v > 0.f ? v : 0.f;
        sA[i] = v * ns[r0 + r];
    }
    __syncthreads();

    const int j = t % 40;
    const int rsub = t / 40;
    float acc[4] = {0.f, 0.f, 0.f, 0.f};
    for (int k = 0; k < 128; k++) {
        float w = __ldg(&W[k * 40 + j]);
#pragma unroll
        for (int r = 0; r < 4; r++) acc[r] = fmaf(sA[(rsub * 4 + r) * 128 + k], w, acc[r]);
    }
#pragma unroll
    for (int r = 0; r < 4; r++) {
        int rr = rsub * 4 + r;
        if (rr < rows) C[(size_t)(r0 + rr) * 40 + j] = acc[r];
    }
}

// ------------------------------------------------------ SpMM (CSR gather) --
__global__ void spmm128_csr(const float* __restrict__ h, const int* __restrict__ csr,
                            const int* __restrict__ roff, const int* __restrict__ cnt,
                            const float* __restrict__ nd, float* __restrict__ x, int n) {
    int node = (int)((blockIdx.x * (size_t)blockDim.x + threadIdx.x) >> 5);
    int lane = threadIdx.x & 31;
    if (node >= n) return;
    int start = __ldg(&roff[node]);
    int deg = __ldg(&cnt[node]);
    float4 acc = make_float4(0.f, 0.f, 0.f, 0.f);
    int e = 0;
    for (; e + 4 <= deg; e += 4) {
        int s0 = __ldg(&csr[start + e + 0]);
        int s1 = __ldg(&csr[start + e + 1]);
        int s2 = __ldg(&csr[start + e + 2]);
        int s3 = __ldg(&csr[start + e + 3]);
        float4 v0 = __ldg((const float4*)h + (size_t)s0 * 32 + lane);
        float4 v1 = __ldg((const float4*)h + (size_t)s1 * 32 + lane);
        float4 v2 = __ldg((const float4*)h + (size_t)s2 * 32 + lane);
        float4 v3 = __ldg((const float4*)h + (size_t)s3 * 32 + lane);
        acc.x += (v0.x + v1.x) + (v2.x + v3.x);
        acc.y += (v0.y + v1.y) + (v2.y + v3.y);
        acc.z += (v0.z + v1.z) + (v2.z + v3.z);
        acc.w += (v0.w + v1.w) + (v2.w + v3.w);
    }
    for (; e < deg; e++) {
        int s = __ldg(&csr[start + e]);
        float4 v = __ldg((const float4*)h + (size_t)s * 32 + lane);
        acc.x += v.x; acc.y += v.y; acc.z += v.z; acc.w += v.w;
    }
    float sc = __ldg(&nd[node]);
    acc.x *= sc; acc.y *= sc; acc.z *= sc; acc.w *= sc;
    *((float4*)x + (size_t)node * 32 + lane) = acc;
}

__global__ void spmm40_csr(const float* __restrict__ h, const int* __restrict__ csr,
                           const int* __restrict__ roff, const int* __restrict__ cnt,
                           const float* __restrict__ nd, const float* __restrict__ b2,
                           float* __restrict__ out, int n) {
    int node = (int)((blockIdx.x * (size_t)blockDim.x + threadIdx.x) >> 5);
    int lane = threadIdx.x & 31;
    if (node >= n || lane >= 10) return;
    int start = __ldg(&roff[node]);
    int deg = __ldg(&cnt[node]);
    float4 acc = make_float4(0.f, 0.f, 0.f, 0.f);
    int e = 0;
    for (; e + 4 <= deg; e += 4) {
        int s0 = __ldg(&csr[start + e + 0]);
        int s1 = __ldg(&csr[start + e + 1]);
        int s2 = __ldg(&csr[start + e + 2]);
        int s3 = __ldg(&csr[start + e + 3]);
        float4 v0 = __ldg((const float4*)h + (size_t)s0 * 10 + lane);
        float4 v1 = __ldg((const float4*)h + (size_t)s1 * 10 + lane);
        float4 v2 = __ldg((const float4*)h + (size_t)s2 * 10 + lane);
        float4 v3 = __ldg((const float4*)h + (size_t)s3 * 10 + lane);
        acc.x += (v0.x + v1.x) + (v2.x + v3.x);
        acc.y += (v0.y + v1.y) + (v2.y + v3.y);
        acc.z += (v0.z + v1.z) + (v2.z + v3.z);
        acc.w += (v0.w + v1.w) + (v2.w + v3.w);
    }
    for (; e < deg; e++) {
        int s = __ldg(&csr[start + e]);
        float4 v = __ldg((const float4*)h + (size_t)s * 10 + lane);
        acc.x += v.x; acc.y += v.y; acc.z += v.z; acc.w += v.w;
    }
    float sc = __ldg(&nd[node]);
    float4 bb = __ldg((const float4*)b2 + lane);
    acc.x = fmaf(acc.x, sc, bb.x);
    acc.y = fmaf(acc.y, sc, bb.y);
    acc.z = fmaf(acc.z, sc, bb.z);
    acc.w = fmaf(acc.w, sc, bb.w);
    *((float4*)out + (size_t)node * 10 + lane) = acc;
}

// --------------------------------------------------------- BatchNorm ----
__global__ void bn_stats(const float* __restrict__ x,
                         float* __restrict__ sums, float* __restrict__ sumsq, int n) {
    int j = threadIdx.x;
    int r0 = blockIdx.x * 256;
    int rend = min(r0 + 256, n);
    float s = 0.f, ss = 0.f;
    for (int r = r0; r < rend; r++) {
        float v = x[(size_t)r * 128 + j];
        s += v;
        ss = fmaf(v, v, ss);
    }
    atomicAdd(&sums[j], s);
    atomicAdd(&sumsq[j], ss);
}

__global__ void bn_coef(const float* __restrict__ sums, const float* __restrict__ sumsq,
                        const float* __restrict__ gam, const float* __restrict__ bet,
                        float* __restrict__ cA, float* __restrict__ cB, float inv_n) {
    int j = threadIdx.x;
    float mean = sums[j] * inv_n;
    float var = sumsq[j] * inv_n - mean * mean;
    float a = rsqrtf(var + 1e-5f) * gam[j];
    cA[j] = a;
    cB[j] = bet[j] - mean * a;
}

// ---------------------------------------------------------------- host --
extern "C" void kernel_launch(void* const* d_in, const int* in_sizes, int n_in,
                              void* d_out, int out_size) {
    const float* feat = (const float*)d_in[0];
    const int* esrc   = (const int*)d_in[1];
    const int* edst   = (const int*)d_in[2];
    const float* W0   = (const float*)d_in[3];
    const float* W1   = (const float*)d_in[4];
    const float* W2   = (const float*)d_in[5];
    const float* b2   = (const float*)d_in[6];
    const float* g0   = (const float*)d_in[7];
    const float* be0  = (const float*)d_in[8];
    const float* g1   = (const float*)d_in[9];
    const float* be1  = (const float*)d_in[10];
    float* out = (float*)d_out;

    const int n = NN;
    const int nE = in_sizes[1];

    float *p_ns, *p_nd, *p_h, *p_x, *p_stats, *p_coef, *p_Whi, *p_Wlo;
    int *p_cs, *p_cd, *p_roff, *p_cursor, *p_part, *p_csr;
    cudaGetSymbolAddress((void**)&p_ns, g_ns);
    cudaGetSymbolAddress((void**)&p_nd, g_nd);
    cudaGetSymbolAddress((void**)&p_h,  g_h);
    cudaGetSymbolAddress((void**)&p_x,  g_x);
    cudaGetSymbolAddress((void**)&p_stats, g_stats);
    cudaGetSymbolAddress((void**)&p_coef,  g_coef);
    cudaGetSymbolAddress((void**)&p_Whi, g_Whi);
    cudaGetSymbolAddress((void**)&p_Wlo, g_Wlo);
    cudaGetSymbolAddress((void**)&p_cs, g_cnt_src);
    cudaGetSymbolAddress((void**)&p_cd, g_cnt_dst);
    cudaGetSymbolAddress((void**)&p_roff, g_roff);
    cudaGetSymbolAddress((void**)&p_cursor, g_cursor);
    cudaGetSymbolAddress((void**)&p_part, g_part);
    cudaGetSymbolAddress((void**)&p_csr, g_csr);
    float* p_sums  = p_stats;
    float* p_sumsq = p_stats + DH;
    float* p_cA = p_coef;
    float* p_cB = p_coef + DH;

    static int smem_set = 0;
    if (!smem_set) {
        cudaFuncSetAttribute(gemm128_tc<0>, cudaFuncAttributeMaxDynamicSharedMemorySize, GEMM_SMEM);
        cudaFuncSetAttribute(gemm128_tc<1>, cudaFuncAttributeMaxDynamicSharedMemorySize, GEMM_SMEM);
        smem_set = 1;
    }

    const int spmm_blocks = (n * 32 + 255) / 256;
    const int stats_blocks = (n + 255) / 256;
    const int gemm_blocks = (n + 127) / 128;
    const float inv_n = 1.0f / (float)n;

    // ---- CSR build + norms ----
    zeroi<<<(n + 255) / 256, 256>>>(p_cs, n);
    zeroi<<<(n + 255) / 256, 256>>>(p_cd, n);
    count_kernel<<<(nE + 255) / 256, 256>>>(esrc, edst, p_cs, p_cd, nE);
    norms_kernel<<<(n + 255) / 256, 256>>>(p_cs, p_cd, p_ns, p_nd, n);
    scan_partial<<<SCAN_BLOCKS, 256>>>(p_cd, p_part, n);
    scan_part_ex<<<1, 128>>>(p_part, SCAN_BLOCKS);
    scan_final<<<SCAN_BLOCKS, 256>>>(p_cd, p_part, p_roff, p_cursor, n);
    scatter_kernel<<<(nE + 255) / 256, 256>>>(esrc, edst, p_cursor, p_csr, nE);

    // ---- layer 0 ----
    split_tf32<<<(DH * DH + 255) / 256, 256>>>(W0, p_Whi, p_Wlo, DH * DH);
    gemm128_tc<0><<<gemm_blocks, 256, GEMM_SMEM>>>(feat, p_ns, nullptr, nullptr,
                                                   p_Whi, p_Wlo, p_h, n);
    spmm128_csr<<<spmm_blocks, 256>>>(p_h, p_csr, p_roff, p_cd, p_nd, p_x, n);
    zerof<<<1, 256>>>(p_stats, 2 * DH);
    bn_stats<<<stats_blocks, 128>>>(p_x, p_sums, p_sumsq, n);
    bn_coef<<<1, 128>>>(p_sums, p_sumsq, g0, be0, p_cA, p_cB, inv_n);

    // ---- layer 1 ----
    split_tf32<<<(DH * DH + 255) / 256, 256>>>(W1, p_Whi, p_Wlo, DH * DH);
    gemm128_tc<1><<<gemm_blocks, 256, GEMM_SMEM>>>(p_x, p_ns, p_cA, p_cB,
                                                   p_Whi, p_Wlo, p_h, n);
    spmm128_csr<<<spmm_blocks, 256>>>(p_h, p_csr, p_roff, p_cd, p_nd, p_x, n);
    zerof<<<1, 256>>>(p_stats, 2 * DH);
    bn_stats<<<stats_blocks, 128>>>(p_x, p_sums, p_sumsq, n);
    bn_coef<<<1, 128>>>(p_sums, p_sumsq, g1, be1, p_cA, p_cB, inv_n);

    // ---- layer 2 ----
    gemm40<<<(n + 31) / 32, 320>>>(p_x, p_ns, p_cA, p_cB, W2, p_h, n);
    spmm40_csr<<<spmm_blocks, 256>>>(p_h, p_csr, p_roff, p_cd, p_nd, b2, out, n);
}

// round 9
// speedup vs baseline: 1.0086x; 1.0086x over previous
#include <cuda_runtime.h>
#include <cuda_bf16.h>
#include <math.h>
#include <stdint.h>

#define NN 100000
#define EE 1600000
#define DH 128
#define DOUT 40
#define SCAN_CHUNK 1024
#define SCAN_BLOCKS ((NN + SCAN_CHUNK - 1) / SCAN_CHUNK)   // 98 <= 128

// -------- scratch (static device globals; no dynamic allocation) --------
__device__ float g_ns[NN];
__device__ float g_nd[NN];
__device__ int   g_cnt_src[NN];
__device__ int   g_cnt_dst[NN];
__device__ int   g_roff[NN];
__device__ int   g_cursor[NN];
__device__ int   g_part[128];
__device__ int   g_csr[EE];
__device__ float g_h [(size_t)NN * DH];
__device__ float g_x [(size_t)NN * DH];
__device__ float g_stats[2 * DH];    // sums / sumsq
__device__ float g_coef[2 * DH];     // a / b
__device__ float g_Whi[DH * DH];
__device__ float g_Wlo[DH * DH];

// ---------------------------------------------------------------- util --
__device__ __forceinline__ uint32_t f2tf32(float v) {
    uint32_t r;
    asm("cvt.rna.tf32.f32 %0, %1;" : "=r"(r) : "f"(v));
    return r;
}

__global__ void zeroi(int* __restrict__ p, int n) {
    int i = blockIdx.x * blockDim.x + threadIdx.x;
    if (i < n) p[i] = 0;
}
__global__ void zerof(float* __restrict__ p, int n) {
    int i = blockIdx.x * blockDim.x + threadIdx.x;
    if (i < n) p[i] = 0.0f;
}

// split W into tf32 hi + tf32(lo) parts
__global__ void split_tf32(const float* __restrict__ W, float* __restrict__ hi,
                           float* __restrict__ lo, int n) {
    int i = blockIdx.x * blockDim.x + threadIdx.x;
    if (i < n) {
        float v = W[i];
        uint32_t h = f2tf32(v);
        float hf = __uint_as_float(h);
        hi[i] = hf;
        lo[i] = __uint_as_float(f2tf32(v - hf));
    }
}

// ------------------------------------------------------------ CSR build --
__global__ void count_kernel(const int* __restrict__ src, const int* __restrict__ dst,
                             int* __restrict__ cs, int* __restrict__ cd, int nE) {
    int i = blockIdx.x * blockDim.x + threadIdx.x;
    if (i < nE) {
        atomicAdd(&cs[src[i]], 1);
        atomicAdd(&cd[dst[i]], 1);
    }
}

__global__ void norms_kernel(const int* __restrict__ cs, const int* __restrict__ cd,
                             float* __restrict__ ns, float* __restrict__ nd, int n) {
    int i = blockIdx.x * blockDim.x + threadIdx.x;
    if (i < n) {
        ns[i] = rsqrtf(fmaxf((float)cs[i], 1.0f));
        nd[i] = rsqrtf(fmaxf((float)cd[i], 1.0f));
    }
}

__global__ void scan_partial(const int* __restrict__ cnt, int* __restrict__ part, int n) {
    __shared__ int sm[256];
    int base = blockIdx.x * SCAN_CHUNK;
    int t = threadIdx.x;
    int s = 0;
    for (int i = t; i < SCAN_CHUNK; i += 256) {
        int idx = base + i;
        if (idx < n) s += cnt[idx];
    }
    sm[t] = s; __syncthreads();
    for (int off = 128; off > 0; off >>= 1) {
        if (t < off) sm[t] += sm[t + off];
        __syncthreads();
    }
    if (t == 0) part[blockIdx.x] = sm[0];
}

__global__ void scan_part_ex(int* __restrict__ part, int nb) {
    __shared__ int sm[128];
    int t = threadIdx.x;
    int orig = (t < nb) ? part[t] : 0;
    sm[t] = orig; __syncthreads();
    for (int off = 1; off < 128; off <<= 1) {
        int v = (t >= off) ? sm[t - off] : 0;
        __syncthreads();
        sm[t] += v;
        __syncthreads();
    }
    if (t < nb) part[t] = sm[t] - orig;
}

__global__ void scan_final(const int* __restrict__ cnt, const int* __restrict__ part,
                           int* __restrict__ roff, int* __restrict__ cursor, int n) {
    __shared__ int sm[256];
    int base = blockIdx.x * SCAN_CHUNK;
    int t = threadIdx.x;
    int v[4]; int s = 0;
#pragma unroll
    for (int i = 0; i < 4; i++) {
        int idx = base + t * 4 + i;
        v[i] = (idx < n) ? cnt[idx] : 0;
        s += v[i];
    }
    int orig = s;
    sm[t] = s; __syncthreads();
    for (int off = 1; off < 256; off <<= 1) {
        int x = (t >= off) ? sm[t - off] : 0;
        __syncthreads();
        sm[t] += x;
        __syncthreads();
    }
    int o = part[blockIdx.x] + sm[t] - orig;
#pragma unroll
    for (int i = 0; i < 4; i++) {
        int idx = base + t * 4 + i;
        if (idx < n) { roff[idx] = o; cursor[idx] = o; o += v[i]; }
    }
}

__global__ void scatter_kernel(const int* __restrict__ src, const int* __restrict__ dst,
                               int* __restrict__ cursor, int* __restrict__ csr, int nE) {
    int i = blockIdx.x * blockDim.x + threadIdx.x;
    if (i < nE) {
        int pos = atomicAdd(&cursor[dst[i]], 1);
        csr[pos] = src[i];
    }
}

// ---------------------------------------------- Tensor-core GEMM (3xTF32) --
// C[N,128] = f(A)[N,128] @ W[128,128]
// MODE 0: f(A) = A * ns[:,None]
// MODE 1: f(A) = relu(A*cA + cB) * ns[:,None]
// Block: 256 threads, tile 128 rows x 128 cols, K in 4 chunks of 32.
// SMEM strides: A stride 36 (== 4 mod 32), W stride 136 (== 8 mod 32) give
// conflict-free fragment LDS for the m16n8k8 lane pattern.
#define A_STR 36
#define W_STR 136
#define SM_AHI 0
#define SM_ALO (128 * A_STR)
#define SM_WHI (2 * 128 * A_STR)
#define SM_WLO (2 * 128 * A_STR + 32 * W_STR)
#define GEMM_SMEM ((2 * 128 * A_STR + 2 * 32 * W_STR) * 4)

__device__ __forceinline__ void mma_tf32(float* d, const uint32_t* a, uint32_t b0, uint32_t b1) {
    asm volatile(
        "mma.sync.aligned.m16n8k8.row.col.f32.tf32.tf32.f32 "
        "{%0,%1,%2,%3},{%4,%5,%6,%7},{%8,%9},{%0,%1,%2,%3};"
        : "+f"(d[0]), "+f"(d[1]), "+f"(d[2]), "+f"(d[3])
        : "r"(a[0]), "r"(a[1]), "r"(a[2]), "r"(a[3]), "r"(b0), "r"(b1));
}

template <int MODE>
__global__ void __launch_bounds__(256, 2)
gemm128_tc(const float* __restrict__ A, const float* __restrict__ ns,
           const float* __restrict__ cA, const float* __restrict__ cB,
           const float* __restrict__ Whi, const float* __restrict__ Wlo,
           float* __restrict__ C, int n) {
    extern __shared__ float sm[];
    const int tid = threadIdx.x;
    const int w = tid >> 5;
    const int lane = tid & 31;
    const int g = lane >> 2;       // group id (0..7)
    const int cq = lane & 3;       // thread-in-group (0..3)
    const int wm = w & 3;          // warp row-block (0..3) -> 32 rows
    const int wn = w >> 2;         // warp col-block (0..1) -> 64 cols
    const int r0 = blockIdx.x * 128;

    float acc[2][8][4];
#pragma unroll
    for (int mt = 0; mt < 2; mt++)
#pragma unroll
        for (int nt = 0; nt < 8; nt++)
#pragma unroll
            for (int i = 0; i < 4; i++) acc[mt][nt][i] = 0.0f;

    for (int chunk = 0; chunk < 4; chunk++) {
        const int kbase = chunk * 32;
        __syncthreads();
        // ---- stage A chunk: 128 rows x 32 k, split hi/lo, fused prologue ----
#pragma unroll
        for (int i = 0; i < 4; i++) {
            int idx = tid + i * 256;          // 0..1023
            int row = idx >> 3;               // 0..127
            int kq = idx & 7;                 // float4 index within 32 k
            int grow = r0 + row;
            float4 v;
            float nsr = 0.0f;
            if (grow < n) {
                v = __ldg((const float4*)A + (size_t)grow * 32 + (kbase >> 2) + kq);
                nsr = __ldg(&ns[grow]);
            } else {
                v = make_float4(0.f, 0.f, 0.f, 0.f);
            }
            if (MODE == 1) {
                float4 a4 = __ldg((const float4*)cA + (kbase >> 2) + kq);
                float4 b4 = __ldg((const float4*)cB + (kbase >> 2) + kq);
                v.x = fmaf(v.x, a4.x, b4.x); v.x = v.x > 0.f ? v.x : 0.f;
                v.y = fmaf(v.y, a4.y, b4.y); v.y = v.y > 0.f ? v.y : 0.f;
                v.z = fmaf(v.z, a4.z, b4.z); v.z = v.z > 0.f ? v.z : 0.f;
                v.w = fmaf(v.w, a4.w, b4.w); v.w = v.w > 0.f ? v.w : 0.f;
            }
            v.x *= nsr; v.y *= nsr; v.z *= nsr; v.w *= nsr;
            float hx = __uint_as_float(f2tf32(v.x));
            float hy = __uint_as_float(f2tf32(v.y));
            float hz = __uint_as_float(f2tf32(v.z));
            float hw = __uint_as_float(f2tf32(v.w));
            float4 hi4 = make_float4(hx, hy, hz, hw);
            float4 lo4 = make_float4(__uint_as_float(f2tf32(v.x - hx)),
                                     __uint_as_float(f2tf32(v.y - hy)),
                                     __uint_as_float(f2tf32(v.z - hz)),
                                     __uint_as_float(f2tf32(v.w - hw)));
            *(float4*)&sm[SM_AHI + row * A_STR + kq * 4] = hi4;
            *(float4*)&sm[SM_ALO + row * A_STR + kq * 4] = lo4;
        }
        // ---- stage W chunk: 32 k x 128 cols (hi and lo, precomputed) ----
#pragma unroll
        for (int i = 0; i < 4; i++) {
            int idx = tid + i * 256;          // 0..1023
            int krow = idx >> 5;              // 0..31
            int cq4 = idx & 31;               // float4 col
            float4 vh = __ldg((const float4*)Whi + (size_t)(kbase + krow) * 32 + cq4);
            float4 vl = __ldg((const float4*)Wlo + (size_t)(kbase + krow) * 32 + cq4);
            *(float4*)&sm[SM_WHI + krow * W_STR + cq4 * 4] = vh;
            *(float4*)&sm[SM_WLO + krow * W_STR + cq4 * 4] = vl;
        }
        __syncthreads();

        // ---- compute: 4 k8-steps ----
#pragma unroll
        for (int k8 = 0; k8 < 4; k8++) {
            const int kc = k8 * 8;
            uint32_t ahi[2][4], alo[2][4];
#pragma unroll
            for (int mt = 0; mt < 2; mt++) {
                int rowb = wm * 32 + mt * 16;
                ahi[mt][0] = __float_as_uint(sm[SM_AHI + (rowb + g) * A_STR + kc + cq]);
                ahi[mt][1] = __float_as_uint(sm[SM_AHI + (rowb + g + 8) * A_STR + kc + cq]);
                ahi[mt][2] = __float_as_uint(sm[SM_AHI + (rowb + g) * A_STR + kc + cq + 4]);
                ahi[mt][3] = __float_as_uint(sm[SM_AHI + (rowb + g + 8) * A_STR + kc + cq + 4]);
                alo[mt][0] = __float_as_uint(sm[SM_ALO + (rowb + g) * A_STR + kc + cq]);
                alo[mt][1] = __float_as_uint(sm[SM_ALO + (rowb + g + 8) * A_STR + kc + cq]);
                alo[mt][2] = __float_as_uint(sm[SM_ALO + (rowb + g) * A_STR + kc + cq + 4]);
                alo[mt][3] = __float_as_uint(sm[SM_ALO + (rowb + g + 8) * A_STR + kc + cq + 4]);
            }
#pragma unroll
            for (int nt = 0; nt < 8; nt++) {
                int colb = wn * 64 + nt * 8;
                uint32_t bhi0 = __float_as_uint(sm[SM_WHI + (kc + cq) * W_STR + colb + g]);
                uint32_t bhi1 = __float_as_uint(sm[SM_WHI + (kc + cq + 4) * W_STR + colb + g]);
                uint32_t blo0 = __float_as_uint(sm[SM_WLO + (kc + cq) * W_STR + colb + g]);
                uint32_t blo1 = __float_as_uint(sm[SM_WLO + (kc + cq + 4) * W_STR + colb + g]);
#pragma unroll
                for (int mt = 0; mt < 2; mt++) {
                    mma_tf32(acc[mt][nt], ahi[mt], bhi0, bhi1);
                    mma_tf32(acc[mt][nt], ahi[mt], blo0, blo1);
                    mma_tf32(acc[mt][nt], alo[mt], bhi0, bhi1);
                }
            }
        }
    }

    // ---- epilogue: write C ----
#pragma unroll
    for (int mt = 0; mt < 2; mt++) {
        int row0 = r0 + wm * 32 + mt * 16 + g;
        int row1 = row0 + 8;
#pragma unroll
        for (int nt = 0; nt < 8; nt++) {
            int col = wn * 64 + nt * 8 + cq * 2;
            if (row0 < n)
                *(float2*)&C[(size_t)row0 * 128 + col] = make_float2(acc[mt][nt][0], acc[mt][nt][1]);
            if (row1 < n)
                *(float2*)&C[(size_t)row1 * 128 + col] = make_float2(acc[mt][nt][2], acc[mt][nt][3]);
        }
    }
}

// ------------------------------------------------- GEMM 40 (FFMA) -------
__global__ void gemm40(const float* __restrict__ A, const float* __restrict__ ns,
                       const float* __restrict__ cA, const float* __restrict__ cB,
                       const float* __restrict__ W, float* __restrict__ C, int n) {
    __shared__ __align__(16) float sA[32 * 128];
    const int t = threadIdx.x;
    int r0 = blockIdx.x * 32;
    if (r0 >= n) return;
    int rows = min(32, n - r0);
    for (int i = t; i < rows * 128; i += 320) {
        int r = i >> 7, k = i & 127;
        float v = A[(size_t)(r0 + r) * 128 + k];
        v = fmaf(v, __ldg(&cA[k]), __ldg(&cB[k]));
        v = v > 0.f ? v : 0.f;
        sA[i] = v * ns[r0 + r];
    }
    __syncthreads();

    const int j = t % 40;
    const int rsub = t / 40;
    float acc[4] = {0.f, 0.f, 0.f, 0.f};
    for (int k = 0; k < 128; k++) {
        float w = __ldg(&W[k * 40 + j]);
#pragma unroll
        for (int r = 0; r < 4; r++) acc[r] = fmaf(sA[(rsub * 4 + r) * 128 + k], w, acc[r]);
    }
#pragma unroll
    for (int r = 0; r < 4; r++) {
        int rr = rsub * 4 + r;
        if (rr < rows) C[(size_t)(r0 + rr) * 40 + j] = acc[r];
    }
}

// ------------------------------------------------------ SpMM (CSR gather) --
__global__ void spmm128_csr(const float* __restrict__ h, const int* __restrict__ csr,
                            const int* __restrict__ roff, const int* __restrict__ cnt,
                            const float* __restrict__ nd, float* __restrict__ x, int n) {
    int node = (int)((blockIdx.x * (size_t)blockDim.x + threadIdx.x) >> 5);
    int lane = threadIdx.x & 31;
    if (node >= n) return;
    int start = __ldg(&roff[node]);
    int deg = __ldg(&cnt[node]);
    float4 acc = make_float4(0.f, 0.f, 0.f, 0.f);
    int e = 0;
    for (; e + 4 <= deg; e += 4) {
        int s0 = __ldg(&csr[start + e + 0]);
        int s1 = __ldg(&csr[start + e + 1]);
        int s2 = __ldg(&csr[start + e + 2]);
        int s3 = __ldg(&csr[start + e + 3]);
        float4 v0 = __ldg((const float4*)h + (size_t)s0 * 32 + lane);
        float4 v1 = __ldg((const float4*)h + (size_t)s1 * 32 + lane);
        float4 v2 = __ldg((const float4*)h + (size_t)s2 * 32 + lane);
        float4 v3 = __ldg((const float4*)h + (size_t)s3 * 32 + lane);
        acc.x += (v0.x + v1.x) + (v2.x + v3.x);
        acc.y += (v0.y + v1.y) + (v2.y + v3.y);
        acc.z += (v0.z + v1.z) + (v2.z + v3.z);
        acc.w += (v0.w + v1.w) + (v2.w + v3.w);
    }
    for (; e < deg; e++) {
        int s = __ldg(&csr[start + e]);
        float4 v = __ldg((const float4*)h + (size_t)s * 32 + lane);
        acc.x += v.x; acc.y += v.y; acc.z += v.z; acc.w += v.w;
    }
    float sc = __ldg(&nd[node]);
    acc.x *= sc; acc.y *= sc; acc.z *= sc; acc.w *= sc;
    *((float4*)x + (size_t)node * 32 + lane) = acc;
}

__global__ void spmm40_csr(const float* __restrict__ h, const int* __restrict__ csr,
                           const int* __restrict__ roff, const int* __restrict__ cnt,
                           const float* __restrict__ nd, const float* __restrict__ b2,
                           float* __restrict__ out, int n) {
    int node = (int)((blockIdx.x * (size_t)blockDim.x + threadIdx.x) >> 5);
    int lane = threadIdx.x & 31;
    if (node >= n || lane >= 10) return;
    int start = __ldg(&roff[node]);
    int deg = __ldg(&cnt[node]);
    float4 acc = make_float4(0.f, 0.f, 0.f, 0.f);
    int e = 0;
    for (; e + 4 <= deg; e += 4) {
        int s0 = __ldg(&csr[start + e + 0]);
        int s1 = __ldg(&csr[start + e + 1]);
        int s2 = __ldg(&csr[start + e + 2]);
        int s3 = __ldg(&csr[start + e + 3]);
        float4 v0 = __ldg((const float4*)h + (size_t)s0 * 10 + lane);
        float4 v1 = __ldg((const float4*)h + (size_t)s1 * 10 + lane);
        float4 v2 = __ldg((const float4*)h + (size_t)s2 * 10 + lane);
        float4 v3 = __ldg((const float4*)h + (size_t)s3 * 10 + lane);
        acc.x += (v0.x + v1.x) + (v2.x + v3.x);
        acc.y += (v0.y + v1.y) + (v2.y + v3.y);
        acc.z += (v0.z + v1.z) + (v2.z + v3.z);
        acc.w += (v0.w + v1.w) + (v2.w + v3.w);
    }
    for (; e < deg; e++) {
        int s = __ldg(&csr[start + e]);
        float4 v = __ldg((const float4*)h + (size_t)s * 10 + lane);
        acc.x += v.x; acc.y += v.y; acc.z += v.z; acc.w += v.w;
    }
    float sc = __ldg(&nd[node]);
    float4 bb = __ldg((const float4*)b2 + lane);
    acc.x = fmaf(acc.x, sc, bb.x);
    acc.y = fmaf(acc.y, sc, bb.y);
    acc.z = fmaf(acc.z, sc, bb.z);
    acc.w = fmaf(acc.w, sc, bb.w);
    *((float4*)out + (size_t)node * 10 + lane) = acc;
}

// --------------------------------------------------------- BatchNorm ----
__global__ void bn_stats(const float* __restrict__ x,
                         float* __restrict__ sums, float* __restrict__ sumsq, int n) {
    int j = threadIdx.x;
    int r0 = blockIdx.x * 256;
    int rend = min(r0 + 256, n);
    float s = 0.f, ss = 0.f;
    for (int r = r0; r < rend; r++) {
        float v = x[(size_t)r * 128 + j];
        s += v;
        ss = fmaf(v, v, ss);
    }
    atomicAdd(&sums[j], s);
    atomicAdd(&sumsq[j], ss);
}

__global__ void bn_coef(const float* __restrict__ sums, const float* __restrict__ sumsq,
                        const float* __restrict__ gam, const float* __restrict__ bet,
                        float* __restrict__ cA, float* __restrict__ cB, float inv_n) {
    int j = threadIdx.x;
    float mean = sums[j] * inv_n;
    float var = sumsq[j] * inv_n - mean * mean;
    float a = rsqrtf(var + 1e-5f) * gam[j];
    cA[j] = a;
    cB[j] = bet[j] - mean * a;
}

// ---------------------------------------------------------------- host --
extern "C" void kernel_launch(void* const* d_in, const int* in_sizes, int n_in,
                              void* d_out, int out_size) {
    const float* feat = (const float*)d_in[0];
    const int* esrc   = (const int*)d_in[1];
    const int* edst   = (const int*)d_in[2];
    const float* W0   = (const float*)d_in[3];
    const float* W1   = (const float*)d_in[4];
    const float* W2   = (const float*)d_in[5];
    const float* b2   = (const float*)d_in[6];
    const float* g0   = (const float*)d_in[7];
    const float* be0  = (const float*)d_in[8];
    const float* g1   = (const float*)d_in[9];
    const float* be1  = (const float*)d_in[10];
    float* out = (float*)d_out;

    const int n = NN;
    const int nE = in_sizes[1];

    float *p_ns, *p_nd, *p_h, *p_x, *p_stats, *p_coef, *p_Whi, *p_Wlo;
    int *p_cs, *p_cd, *p_roff, *p_cursor, *p_part, *p_csr;
    cudaGetSymbolAddress((void**)&p_ns, g_ns);
    cudaGetSymbolAddress((void**)&p_nd, g_nd);
    cudaGetSymbolAddress((void**)&p_h,  g_h);
    cudaGetSymbolAddress((void**)&p_x,  g_x);
    cudaGetSymbolAddress((void**)&p_stats, g_stats);
    cudaGetSymbolAddress((void**)&p_coef,  g_coef);
    cudaGetSymbolAddress((void**)&p_Whi, g_Whi);
    cudaGetSymbolAddress((void**)&p_Wlo, g_Wlo);
    cudaGetSymbolAddress((void**)&p_cs, g_cnt_src);
    cudaGetSymbolAddress((void**)&p_cd, g_cnt_dst);
    cudaGetSymbolAddress((void**)&p_roff, g_roff);
    cudaGetSymbolAddress((void**)&p_cursor, g_cursor);
    cudaGetSymbolAddress((void**)&p_part, g_part);
    cudaGetSymbolAddress((void**)&p_csr, g_csr);
    float* p_sums  = p_stats;
    float* p_sumsq = p_stats + DH;
    float* p_cA = p_coef;
    float* p_cB = p_coef + DH;

    static int smem_set = 0;
    if (!smem_set) {
        cudaFuncSetAttribute(gemm128_tc<0>, cudaFuncAttributeMaxDynamicSharedMemorySize, GEMM_SMEM);
        cudaFuncSetAttribute(gemm128_tc<1>, cudaFuncAttributeMaxDynamicSharedMemorySize, GEMM_SMEM);
        smem_set = 1;
    }

    const int spmm_blocks = (n * 32 + 255) / 256;
    const int stats_blocks = (n + 255) / 256;
    const int gemm_blocks = (n + 127) / 128;
    const float inv_n = 1.0f / (float)n;

    // ---- CSR build + norms ----
    zeroi<<<(n + 255) / 256, 256>>>(p_cs, n);
    zeroi<<<(n + 255) / 256, 256>>>(p_cd, n);
    count_kernel<<<(nE + 255) / 256, 256>>>(esrc, edst, p_cs, p_cd, nE);
    norms_kernel<<<(n + 255) / 256, 256>>>(p_cs, p_cd, p_ns, p_nd, n);
    scan_partial<<<SCAN_BLOCKS, 256>>>(p_cd, p_part, n);
    scan_part_ex<<<1, 128>>>(p_part, SCAN_BLOCKS);
    scan_final<<<SCAN_BLOCKS, 256>>>(p_cd, p_part, p_roff, p_cursor, n);
    scatter_kernel<<<(nE + 255) / 256, 256>>>(esrc, edst, p_cursor, p_csr, nE);

    // ---- layer 0 ----
    split_tf32<<<(DH * DH + 255) / 256, 256>>>(W0, p_Whi, p_Wlo, DH * DH);
    gemm128_tc<0><<<gemm_blocks, 256, GEMM_SMEM>>>(feat, p_ns, nullptr, nullptr,
                                                   p_Whi, p_Wlo, p_h, n);
    spmm128_csr<<<spmm_blocks, 256>>>(p_h, p_csr, p_roff, p_cd, p_nd, p_x, n);
    zerof<<<1, 256>>>(p_stats, 2 * DH);
    bn_stats<<<stats_blocks, 128>>>(p_x, p_sums, p_sumsq, n);
    bn_coef<<<1, 128>>>(p_sums, p_sumsq, g0, be0, p_cA, p_cB, inv_n);

    // ---- layer 1 ----
    split_tf32<<<(DH * DH + 255) / 256, 256>>>(W1, p_Whi, p_Wlo, DH * DH);
    gemm128_tc<1><<<gemm_blocks, 256, GEMM_SMEM>>>(p_x, p_ns, p_cA, p_cB,
                                                   p_Whi, p_Wlo, p_h, n);
    spmm128_csr<<<spmm_blocks, 256>>>(p_h, p_csr, p_roff, p_cd, p_nd, p_x, n);
    zerof<<<1, 256>>>(p_stats, 2 * DH);
    bn_stats<<<stats_blocks, 128>>>(p_x, p_sums, p_sumsq, n);
    bn_coef<<<1, 128>>>(p_sums, p_sumsq, g1, be1, p_cA, p_cB, inv_n);

    // ---- layer 2 ----
    gemm40<<<(n + 31) / 32, 320>>>(p_x, p_ns, p_cA, p_cB, W2, p_h, n);
    spmm40_csr<<<spmm_blocks, 256>>>(p_h, p_csr, p_roff, p_cd, p_nd, b2, out, n);
}